// round 8
// baseline (speedup 1.0000x reference)
#include <cuda_runtime.h>
#include <cuda_bf16.h>

#define THREADS 256
#define MAX_EDGES 100000
#define TILE_R 256
#define XS_STRIDE 68         // %4==0 (aligned float4 rows), rows 1 apart -> bank offset 4

// Precomputed edge contributions: PE[e][0:64] = E[e]@W1^T, PE[e][64:128] = E[e]@W2^T
__device__ float g_PE[MAX_EDGES * 128];

// ---------------------------------------------------------------------------
// Kernel A: edge precompute. Tile 128 rows x 128 cols, 256 threads,
// 8x8 per thread, f32x2 FMA. Warps 0-3: cols 0-63, warps 4-7: cols 64-127.
// smem: WsA/WsB[64][64] (even/odd col-quads) + Xs[128][68]
// ---------------------------------------------------------------------------
__global__ __launch_bounds__(THREADS, 2) void edge_precompute_v2(
    const float* __restrict__ HE, const float* __restrict__ W, int n_edges)
{
    extern __shared__ float sm[];
    float* WsA = sm;                    // 64*64
    float* WsB = sm + 64 * 64;          // 64*64
    float* Xs  = sm + 2 * 64 * 64;      // 128*68

    int tid  = threadIdx.x;
    int lane = tid & 31;
    int warp = tid >> 5;
    int rw   = lane & 3;
    int cx   = lane >> 2;               // 0..7
    int colhalf = warp >> 2;            // 0 or 1
    int rowbase = (warp & 3) * 32 + rw; // rows rowbase + 4j

    // Stage combined W1|W2 table, split even/odd col-quads.
    for (int i = tid; i < 64 * 128; i += THREADS) {
        int o = i >> 6;                 // 0..127
        int k = i & 63;                 // coalesced
        float v = (o < 64) ? W[o * 192 + k] : W[(o - 64) * 192 + 64 + k];
        int q = o >> 2;
        float* dst = (q & 1) ? WsB : WsA;
        dst[k * 64 + (q >> 1) * 4 + (o & 3)] = v;
    }

    int e0 = blockIdx.x * 128;
    int vr = n_edges - e0; if (vr > 128) vr = 128;

    const float4* src = reinterpret_cast<const float4*>(HE);
    #pragma unroll
    for (int it = 0; it < 8; it++) {
        int i = tid + it * THREADS;
        int r = i >> 4, kq = i & 15;
        float4 v = make_float4(0.f, 0.f, 0.f, 0.f);
        if (r < vr) v = src[(size_t)(e0 + r) * 16 + kq];
        *reinterpret_cast<float4*>(&Xs[r * XS_STRIDE + kq * 4]) = v;
    }
    __syncthreads();

    unsigned long long acc[8][4];
    #pragma unroll
    for (int j = 0; j < 8; j++) { acc[j][0]=0; acc[j][1]=0; acc[j][2]=0; acc[j][3]=0; }

    #pragma unroll 4
    for (int kq = 0; kq < 16; kq++) {
        float4 xv[8];
        #pragma unroll
        for (int j = 0; j < 8; j++)
            xv[j] = *reinterpret_cast<const float4*>(&Xs[(rowbase + 4 * j) * XS_STRIDE + kq * 4]);
        #pragma unroll
        for (int kk = 0; kk < 4; kk++) {
            int k = kq * 4 + kk;
            ulonglong2 wA = *reinterpret_cast<const ulonglong2*>(&WsA[k * 64 + colhalf * 32 + cx * 4]);
            ulonglong2 wB = *reinterpret_cast<const ulonglong2*>(&WsB[k * 64 + colhalf * 32 + cx * 4]);
            #pragma unroll
            for (int j = 0; j < 8; j++) {
                float x = reinterpret_cast<const float*>(&xv[j])[kk];
                unsigned long long xd;
                asm("mov.b64 %0, {%1, %1};" : "=l"(xd) : "f"(x));
                asm("fma.rn.f32x2 %0, %1, %2, %0;" : "+l"(acc[j][0]) : "l"(xd), "l"(wA.x));
                asm("fma.rn.f32x2 %0, %1, %2, %0;" : "+l"(acc[j][1]) : "l"(wA.y), "l"(xd));
                asm("fma.rn.f32x2 %0, %1, %2, %0;" : "+l"(acc[j][2]) : "l"(xd), "l"(wB.x));
                asm("fma.rn.f32x2 %0, %1, %2, %0;" : "+l"(acc[j][3]) : "l"(wB.y), "l"(xd));
            }
        }
    }

    #pragma unroll
    for (int j = 0; j < 8; j++) {
        int row = rowbase + 4 * j;
        if (row < vr) {
            float f[8];
            asm("mov.b64 {%0, %1}, %2;" : "=f"(f[0]), "=f"(f[1]) : "l"(acc[j][0]));
            asm("mov.b64 {%0, %1}, %2;" : "=f"(f[2]), "=f"(f[3]) : "l"(acc[j][1]));
            asm("mov.b64 {%0, %1}, %2;" : "=f"(f[4]), "=f"(f[5]) : "l"(acc[j][2]));
            asm("mov.b64 {%0, %1}, %2;" : "=f"(f[6]), "=f"(f[7]) : "l"(acc[j][3]));
            float* orow = &g_PE[(size_t)(e0 + row) * 128 + colhalf * 64 + cx * 8];
            *reinterpret_cast<float4*>(orow)     = make_float4(f[0], f[1], f[2], f[3]);
            *reinterpret_cast<float4*>(orow + 4) = make_float4(f[4], f[5], f[6], f[7]);
        }
    }
}

// ---------------------------------------------------------------------------
// Kernel B v3: tile 256 rows x 64 cols, 8x8 per thread, f32x2, vectorized
// x loads, conflict-free W via even/odd quad split.
// smem: WsA/WsB[64][32] + Xs[256][68]
// ---------------------------------------------------------------------------
__global__ __launch_bounds__(THREADS, 2) void e2v_fused_v3(
    const float* __restrict__ node, const int* __restrict__ aff,
    const float* __restrict__ W, const float* __restrict__ bias,
    float* __restrict__ out, int n_inc, int n_edges)
{
    extern __shared__ float sm[];
    float* WsA = sm;                    // 64*32
    float* WsB = sm + 64 * 32;          // 64*32
    float* Xs  = sm + 2 * 64 * 32;      // 256*68

    int tid  = threadIdx.x;
    int lane = tid & 31;
    int warp = tid >> 5;
    int rw   = lane & 3;
    int cx   = lane >> 2;               // 0..7, cols cx*8..cx*8+7
    int rowbase = warp * 32 + rw;       // rows rowbase + 4j within tile

    // Stage W3, split even/odd col-quads.
    for (int i = tid; i < 64 * 64; i += THREADS) {
        int o = i >> 6;
        int k = i & 63;                 // coalesced
        float v = W[o * 192 + 128 + k];
        int q = o >> 2;
        float* dst = (q & 1) ? WsB : WsA;
        dst[k * 32 + (q >> 1) * 4 + (o & 3)] = v;
    }

    float4 b0 = *reinterpret_cast<const float4*>(bias + cx * 8);
    float4 b1 = *reinterpret_cast<const float4*>(bias + cx * 8 + 4);
    unsigned long long binit[4];
    asm("mov.b64 %0, {%1, %2};" : "=l"(binit[0]) : "f"(b0.x), "f"(b0.y));
    asm("mov.b64 %0, {%1, %2};" : "=l"(binit[1]) : "f"(b0.z), "f"(b0.w));
    asm("mov.b64 %0, {%1, %2};" : "=l"(binit[2]) : "f"(b1.x), "f"(b1.y));
    asm("mov.b64 %0, {%1, %2};" : "=l"(binit[3]) : "f"(b1.z), "f"(b1.w));

    const float4* node4 = reinterpret_cast<const float4*>(node);
    const float4* PE4   = reinterpret_cast<const float4*>(g_PE);

    int n_tiles = (n_inc + TILE_R - 1) / TILE_R;
    for (int t = blockIdx.x; t < n_tiles; t += gridDim.x) {
        __syncthreads();
        int r0 = t * TILE_R;
        int vr = n_inc - r0; if (vr > TILE_R) vr = TILE_R;

        #pragma unroll
        for (int it = 0; it < (TILE_R * 16) / THREADS; it++) {
            int i = tid + it * THREADS;
            int r = i >> 4, kq = i & 15;
            float4 v = make_float4(0.f, 0.f, 0.f, 0.f);
            if (r < vr) v = node4[(size_t)(r0 + r) * 16 + kq];
            *reinterpret_cast<float4*>(&Xs[r * XS_STRIDE + kq * 4]) = v;
        }
        __syncthreads();

        unsigned long long acc[8][4];
        #pragma unroll
        for (int j = 0; j < 8; j++) {
            acc[j][0] = binit[0]; acc[j][1] = binit[1];
            acc[j][2] = binit[2]; acc[j][3] = binit[3];
        }

        #pragma unroll 4
        for (int kq = 0; kq < 16; kq++) {
            float4 xv[8];
            #pragma unroll
            for (int j = 0; j < 8; j++)
                xv[j] = *reinterpret_cast<const float4*>(&Xs[(rowbase + 4 * j) * XS_STRIDE + kq * 4]);
            #pragma unroll
            for (int kk = 0; kk < 4; kk++) {
                int k = kq * 4 + kk;
                ulonglong2 wA = *reinterpret_cast<const ulonglong2*>(&WsA[k * 32 + cx * 4]);
                ulonglong2 wB = *reinterpret_cast<const ulonglong2*>(&WsB[k * 32 + cx * 4]);
                #pragma unroll
                for (int j = 0; j < 8; j++) {
                    float x = reinterpret_cast<const float*>(&xv[j])[kk];
                    unsigned long long xd;
                    asm("mov.b64 %0, {%1, %1};" : "=l"(xd) : "f"(x));
                    asm("fma.rn.f32x2 %0, %1, %2, %0;" : "+l"(acc[j][0]) : "l"(xd), "l"(wA.x));
                    asm("fma.rn.f32x2 %0, %1, %2, %0;" : "+l"(acc[j][1]) : "l"(wA.y), "l"(xd));
                    asm("fma.rn.f32x2 %0, %1, %2, %0;" : "+l"(acc[j][2]) : "l"(xd), "l"(wB.x));
                    asm("fma.rn.f32x2 %0, %1, %2, %0;" : "+l"(acc[j][3]) : "l"(wB.y), "l"(xd));
                }
            }
        }

        #pragma unroll
        for (int j = 0; j < 8; j++) {
            int gi = r0 + rowbase + 4 * j;
            if (gi < n_inc) {
                int e0 = aff[gi];
                int e1 = aff[(size_t)n_inc + gi];
                e0 = min(max(e0, 0), n_edges - 1);
                e1 = min(max(e1, 0), n_edges - 1);
                float4 p0a = PE4[(size_t)e0 * 32 + cx * 2];
                float4 p0b = PE4[(size_t)e0 * 32 + cx * 2 + 1];
                float4 p1a = PE4[(size_t)e1 * 32 + 16 + cx * 2];
                float4 p1b = PE4[(size_t)e1 * 32 + 16 + cx * 2 + 1];
                float f[8];
                asm("mov.b64 {%0, %1}, %2;" : "=f"(f[0]), "=f"(f[1]) : "l"(acc[j][0]));
                asm("mov.b64 {%0, %1}, %2;" : "=f"(f[2]), "=f"(f[3]) : "l"(acc[j][1]));
                asm("mov.b64 {%0, %1}, %2;" : "=f"(f[4]), "=f"(f[5]) : "l"(acc[j][2]));
                asm("mov.b64 {%0, %1}, %2;" : "=f"(f[6]), "=f"(f[7]) : "l"(acc[j][3]));
                float4 ra, rb;
                ra.x = f[0] + p0a.x + p1a.x;  ra.y = f[1] + p0a.y + p1a.y;
                ra.z = f[2] + p0a.z + p1a.z;  ra.w = f[3] + p0a.w + p1a.w;
                rb.x = f[4] + p0b.x + p1b.x;  rb.y = f[5] + p0b.y + p1b.y;
                rb.z = f[6] + p0b.z + p1b.z;  rb.w = f[7] + p0b.w + p1b.w;
                ra.x = ra.x > 0.f ? ra.x : 0.f;  ra.y = ra.y > 0.f ? ra.y : 0.f;
                ra.z = ra.z > 0.f ? ra.z : 0.f;  ra.w = ra.w > 0.f ? ra.w : 0.f;
                rb.x = rb.x > 0.f ? rb.x : 0.f;  rb.y = rb.y > 0.f ? rb.y : 0.f;
                rb.z = rb.z > 0.f ? rb.z : 0.f;  rb.w = rb.w > 0.f ? rb.w : 0.f;
                float* orow = out + (size_t)gi * 64 + cx * 8;
                *reinterpret_cast<float4*>(orow)     = ra;
                *reinterpret_cast<float4*>(orow + 4) = rb;
            }
        }
    }
}

extern "C" void kernel_launch(void* const* d_in, const int* in_sizes, int n_in,
                              void* d_out, int out_size) {
    const float* HE   = (const float*)d_in[0];      // [N_EDGES, 64]
    const float* node = (const float*)d_in[1];      // [N_INC, 64]
    const int*   aff  = (const int*)d_in[2];        // [2, N_INC] int32
    const float* W    = (const float*)d_in[3];      // [64, 192]
    const float* bias = (const float*)d_in[4];      // [64]
    float* out = (float*)d_out;

    int n_edges = in_sizes[0] / 64;
    int n_inc   = in_sizes[1] / 64;
    if (n_edges > MAX_EDGES) n_edges = MAX_EDGES;

    size_t smem_a = (size_t)(2 * 64 * 64 + 128 * XS_STRIDE) * sizeof(float);   // ~67 KB
    size_t smem_b = (size_t)(2 * 64 * 32 + TILE_R * XS_STRIDE) * sizeof(float); // ~84 KB
    cudaFuncSetAttribute(edge_precompute_v2, cudaFuncAttributeMaxDynamicSharedMemorySize, (int)smem_a);
    cudaFuncSetAttribute(e2v_fused_v3, cudaFuncAttributeMaxDynamicSharedMemorySize, (int)smem_b);

    int grid_a = (n_edges + 127) / 128;
    edge_precompute_v2<<<grid_a, THREADS, smem_a>>>(HE, W, n_edges);

    int n_tiles = (n_inc + TILE_R - 1) / TILE_R;
    int grid_b = n_tiles < 296 ? n_tiles : 296;     // 148 SMs x 2 CTAs
    e2v_fused_v3<<<grid_b, THREADS, smem_b>>>(node, aff, W, bias, out, n_inc, n_edges);
}

// round 9
// speedup vs baseline: 1.0020x; 1.0020x over previous
#include <cuda_runtime.h>
#include <cuda_bf16.h>

#define THREADS 256
#define MAX_EDGES 100000
#define TILE_R 256
#define XS_STRIDE 68         // %4==0 (aligned float4 rows), rows 1 apart -> bank offset 4

// Precomputed edge contributions: PE[e][0:64] = E[e]@W1^T, PE[e][64:128] = E[e]@W2^T
__device__ float g_PE[MAX_EDGES * 128];

// ---------------------------------------------------------------------------
// Kernel A: edge precompute. Tile 128 rows x 128 cols, 256 threads,
// 8x8 per thread, f32x2 FMA. Warps 0-3: cols 0-63, warps 4-7: cols 64-127.
// smem: WsA/WsB[64][64] (even/odd col-quads) + Xs[128][68]
// ---------------------------------------------------------------------------
__global__ __launch_bounds__(THREADS, 2) void edge_precompute_v2(
    const float* __restrict__ HE, const float* __restrict__ W, int n_edges)
{
    extern __shared__ float sm[];
    float* WsA = sm;                    // 64*64
    float* WsB = sm + 64 * 64;          // 64*64
    float* Xs  = sm + 2 * 64 * 64;      // 128*68

    int tid  = threadIdx.x;
    int lane = tid & 31;
    int warp = tid >> 5;
    int rw   = lane & 3;
    int cx   = lane >> 2;               // 0..7
    int colhalf = warp >> 2;            // 0 or 1
    int rowbase = (warp & 3) * 32 + rw; // rows rowbase + 4j

    // Stage combined W1|W2 table, split even/odd col-quads.
    for (int i = tid; i < 64 * 128; i += THREADS) {
        int o = i >> 6;                 // 0..127
        int k = i & 63;                 // coalesced
        float v = (o < 64) ? W[o * 192 + k] : W[(o - 64) * 192 + 64 + k];
        int q = o >> 2;
        float* dst = (q & 1) ? WsB : WsA;
        dst[k * 64 + (q >> 1) * 4 + (o & 3)] = v;
    }

    int e0 = blockIdx.x * 128;
    int vr = n_edges - e0; if (vr > 128) vr = 128;

    const float4* src = reinterpret_cast<const float4*>(HE);
    #pragma unroll
    for (int it = 0; it < 8; it++) {
        int i = tid + it * THREADS;
        int r = i >> 4, kq = i & 15;
        float4 v = make_float4(0.f, 0.f, 0.f, 0.f);
        if (r < vr) v = src[(size_t)(e0 + r) * 16 + kq];
        *reinterpret_cast<float4*>(&Xs[r * XS_STRIDE + kq * 4]) = v;
    }
    __syncthreads();

    unsigned long long acc[8][4];
    #pragma unroll
    for (int j = 0; j < 8; j++) { acc[j][0]=0; acc[j][1]=0; acc[j][2]=0; acc[j][3]=0; }

    #pragma unroll 4
    for (int kq = 0; kq < 16; kq++) {
        float4 xv[8];
        #pragma unroll
        for (int j = 0; j < 8; j++)
            xv[j] = *reinterpret_cast<const float4*>(&Xs[(rowbase + 4 * j) * XS_STRIDE + kq * 4]);
        #pragma unroll
        for (int kk = 0; kk < 4; kk++) {
            int k = kq * 4 + kk;
            ulonglong2 wA = *reinterpret_cast<const ulonglong2*>(&WsA[k * 64 + colhalf * 32 + cx * 4]);
            ulonglong2 wB = *reinterpret_cast<const ulonglong2*>(&WsB[k * 64 + colhalf * 32 + cx * 4]);
            #pragma unroll
            for (int j = 0; j < 8; j++) {
                float x = reinterpret_cast<const float*>(&xv[j])[kk];
                unsigned long long xd;
                asm("mov.b64 %0, {%1, %1};" : "=l"(xd) : "f"(x));
                asm("fma.rn.f32x2 %0, %1, %2, %0;" : "+l"(acc[j][0]) : "l"(xd), "l"(wA.x));
                asm("fma.rn.f32x2 %0, %1, %2, %0;" : "+l"(acc[j][1]) : "l"(wA.y), "l"(xd));
                asm("fma.rn.f32x2 %0, %1, %2, %0;" : "+l"(acc[j][2]) : "l"(xd), "l"(wB.x));
                asm("fma.rn.f32x2 %0, %1, %2, %0;" : "+l"(acc[j][3]) : "l"(wB.y), "l"(xd));
            }
        }
    }

    #pragma unroll
    for (int j = 0; j < 8; j++) {
        int row = rowbase + 4 * j;
        if (row < vr) {
            float f[8];
            asm("mov.b64 {%0, %1}, %2;" : "=f"(f[0]), "=f"(f[1]) : "l"(acc[j][0]));
            asm("mov.b64 {%0, %1}, %2;" : "=f"(f[2]), "=f"(f[3]) : "l"(acc[j][1]));
            asm("mov.b64 {%0, %1}, %2;" : "=f"(f[4]), "=f"(f[5]) : "l"(acc[j][2]));
            asm("mov.b64 {%0, %1}, %2;" : "=f"(f[6]), "=f"(f[7]) : "l"(acc[j][3]));
            float* orow = &g_PE[(size_t)(e0 + row) * 128 + colhalf * 64 + cx * 8];
            *reinterpret_cast<float4*>(orow)     = make_float4(f[0], f[1], f[2], f[3]);
            *reinterpret_cast<float4*>(orow + 4) = make_float4(f[4], f[5], f[6], f[7]);
        }
    }
}

// ---------------------------------------------------------------------------
// Kernel B v3: tile 256 rows x 64 cols, 8x8 per thread, f32x2, vectorized
// x loads, conflict-free W via even/odd quad split.
// smem: WsA/WsB[64][32] + Xs[256][68]
// ---------------------------------------------------------------------------
__global__ __launch_bounds__(THREADS, 2) void e2v_fused_v3(
    const float* __restrict__ node, const int* __restrict__ aff,
    const float* __restrict__ W, const float* __restrict__ bias,
    float* __restrict__ out, int n_inc, int n_edges)
{
    extern __shared__ float sm[];
    float* WsA = sm;                    // 64*32
    float* WsB = sm + 64 * 32;          // 64*32
    float* Xs  = sm + 2 * 64 * 32;      // 256*68

    int tid  = threadIdx.x;
    int lane = tid & 31;
    int warp = tid >> 5;
    int rw   = lane & 3;
    int cx   = lane >> 2;               // 0..7, cols cx*8..cx*8+7
    int rowbase = warp * 32 + rw;       // rows rowbase + 4j within tile

    // Stage W3, split even/odd col-quads.
    for (int i = tid; i < 64 * 64; i += THREADS) {
        int o = i >> 6;
        int k = i & 63;                 // coalesced
        float v = W[o * 192 + 128 + k];
        int q = o >> 2;
        float* dst = (q & 1) ? WsB : WsA;
        dst[k * 32 + (q >> 1) * 4 + (o & 3)] = v;
    }

    float4 b0 = *reinterpret_cast<const float4*>(bias + cx * 8);
    float4 b1 = *reinterpret_cast<const float4*>(bias + cx * 8 + 4);
    unsigned long long binit[4];
    asm("mov.b64 %0, {%1, %2};" : "=l"(binit[0]) : "f"(b0.x), "f"(b0.y));
    asm("mov.b64 %0, {%1, %2};" : "=l"(binit[1]) : "f"(b0.z), "f"(b0.w));
    asm("mov.b64 %0, {%1, %2};" : "=l"(binit[2]) : "f"(b1.x), "f"(b1.y));
    asm("mov.b64 %0, {%1, %2};" : "=l"(binit[3]) : "f"(b1.z), "f"(b1.w));

    const float4* node4 = reinterpret_cast<const float4*>(node);
    const float4* PE4   = reinterpret_cast<const float4*>(g_PE);

    int n_tiles = (n_inc + TILE_R - 1) / TILE_R;
    for (int t = blockIdx.x; t < n_tiles; t += gridDim.x) {
        __syncthreads();
        int r0 = t * TILE_R;
        int vr = n_inc - r0; if (vr > TILE_R) vr = TILE_R;

        #pragma unroll
        for (int it = 0; it < (TILE_R * 16) / THREADS; it++) {
            int i = tid + it * THREADS;
            int r = i >> 4, kq = i & 15;
            float4 v = make_float4(0.f, 0.f, 0.f, 0.f);
            if (r < vr) v = node4[(size_t)(r0 + r) * 16 + kq];
            *reinterpret_cast<float4*>(&Xs[r * XS_STRIDE + kq * 4]) = v;
        }
        __syncthreads();

        unsigned long long acc[8][4];
        #pragma unroll
        for (int j = 0; j < 8; j++) {
            acc[j][0] = binit[0]; acc[j][1] = binit[1];
            acc[j][2] = binit[2]; acc[j][3] = binit[3];
        }

        #pragma unroll 4
        for (int kq = 0; kq < 16; kq++) {
            float4 xv[8];
            #pragma unroll
            for (int j = 0; j < 8; j++)
                xv[j] = *reinterpret_cast<const float4*>(&Xs[(rowbase + 4 * j) * XS_STRIDE + kq * 4]);
            #pragma unroll
            for (int kk = 0; kk < 4; kk++) {
                int k = kq * 4 + kk;
                ulonglong2 wA = *reinterpret_cast<const ulonglong2*>(&WsA[k * 32 + cx * 4]);
                ulonglong2 wB = *reinterpret_cast<const ulonglong2*>(&WsB[k * 32 + cx * 4]);
                #pragma unroll
                for (int j = 0; j < 8; j++) {
                    float x = reinterpret_cast<const float*>(&xv[j])[kk];
                    unsigned long long xd;
                    asm("mov.b64 %0, {%1, %1};" : "=l"(xd) : "f"(x));
                    asm("fma.rn.f32x2 %0, %1, %2, %0;" : "+l"(acc[j][0]) : "l"(xd), "l"(wA.x));
                    asm("fma.rn.f32x2 %0, %1, %2, %0;" : "+l"(acc[j][1]) : "l"(wA.y), "l"(xd));
                    asm("fma.rn.f32x2 %0, %1, %2, %0;" : "+l"(acc[j][2]) : "l"(xd), "l"(wB.x));
                    asm("fma.rn.f32x2 %0, %1, %2, %0;" : "+l"(acc[j][3]) : "l"(wB.y), "l"(xd));
                }
            }
        }

        #pragma unroll
        for (int j = 0; j < 8; j++) {
            int gi = r0 + rowbase + 4 * j;
            if (gi < n_inc) {
                int e0 = aff[gi];
                int e1 = aff[(size_t)n_inc + gi];
                e0 = min(max(e0, 0), n_edges - 1);
                e1 = min(max(e1, 0), n_edges - 1);
                float4 p0a = PE4[(size_t)e0 * 32 + cx * 2];
                float4 p0b = PE4[(size_t)e0 * 32 + cx * 2 + 1];
                float4 p1a = PE4[(size_t)e1 * 32 + 16 + cx * 2];
                float4 p1b = PE4[(size_t)e1 * 32 + 16 + cx * 2 + 1];
                float f[8];
                asm("mov.b64 {%0, %1}, %2;" : "=f"(f[0]), "=f"(f[1]) : "l"(acc[j][0]));
                asm("mov.b64 {%0, %1}, %2;" : "=f"(f[2]), "=f"(f[3]) : "l"(acc[j][1]));
                asm("mov.b64 {%0, %1}, %2;" : "=f"(f[4]), "=f"(f[5]) : "l"(acc[j][2]));
                asm("mov.b64 {%0, %1}, %2;" : "=f"(f[6]), "=f"(f[7]) : "l"(acc[j][3]));
                float4 ra, rb;
                ra.x = f[0] + p0a.x + p1a.x;  ra.y = f[1] + p0a.y + p1a.y;
                ra.z = f[2] + p0a.z + p1a.z;  ra.w = f[3] + p0a.w + p1a.w;
                rb.x = f[4] + p0b.x + p1b.x;  rb.y = f[5] + p0b.y + p1b.y;
                rb.z = f[6] + p0b.z + p1b.z;  rb.w = f[7] + p0b.w + p1b.w;
                ra.x = ra.x > 0.f ? ra.x : 0.f;  ra.y = ra.y > 0.f ? ra.y : 0.f;
                ra.z = ra.z > 0.f ? ra.z : 0.f;  ra.w = ra.w > 0.f ? ra.w : 0.f;
                rb.x = rb.x > 0.f ? rb.x : 0.f;  rb.y = rb.y > 0.f ? rb.y : 0.f;
                rb.z = rb.z > 0.f ? rb.z : 0.f;  rb.w = rb.w > 0.f ? rb.w : 0.f;
                float* orow = out + (size_t)gi * 64 + cx * 8;
                *reinterpret_cast<float4*>(orow)     = ra;
                *reinterpret_cast<float4*>(orow + 4) = rb;
            }
        }
    }
}

extern "C" void kernel_launch(void* const* d_in, const int* in_sizes, int n_in,
                              void* d_out, int out_size) {
    const float* HE   = (const float*)d_in[0];      // [N_EDGES, 64]
    const float* node = (const float*)d_in[1];      // [N_INC, 64]
    const int*   aff  = (const int*)d_in[2];        // [2, N_INC] int32
    const float* W    = (const float*)d_in[3];      // [64, 192]
    const float* bias = (const float*)d_in[4];      // [64]
    float* out = (float*)d_out;

    int n_edges = in_sizes[0] / 64;
    int n_inc   = in_sizes[1] / 64;
    if (n_edges > MAX_EDGES) n_edges = MAX_EDGES;

    size_t smem_a = (size_t)(2 * 64 * 64 + 128 * XS_STRIDE) * sizeof(float);   // ~67 KB
    size_t smem_b = (size_t)(2 * 64 * 32 + TILE_R * XS_STRIDE) * sizeof(float); // ~84 KB
    cudaFuncSetAttribute(edge_precompute_v2, cudaFuncAttributeMaxDynamicSharedMemorySize, (int)smem_a);
    cudaFuncSetAttribute(e2v_fused_v3, cudaFuncAttributeMaxDynamicSharedMemorySize, (int)smem_b);

    int grid_a = (n_edges + 127) / 128;
    edge_precompute_v2<<<grid_a, THREADS, smem_a>>>(HE, W, n_edges);

    int n_tiles = (n_inc + TILE_R - 1) / TILE_R;
    int grid_b = n_tiles < 296 ? n_tiles : 296;     // 148 SMs x 2 CTAs
    e2v_fused_v3<<<grid_b, THREADS, smem_b>>>(node, aff, W, bias, out, n_inc, n_edges);
}